// round 4
// baseline (speedup 1.0000x reference)
#include <cuda_runtime.h>

#define BATCH   16
#define KPTS    2048
#define NPOINT  2048

#define TPB_A   256
#define IBLK    2
#define ICHUNK  (TPB_A * IBLK)        // 512 i-points per CTA
#define NI_CH   (KPTS / ICHUNK)       // 4
#define JS      16                    // j-splits
#define JCH     (KPTS / JS)           // 128 j-points per CTA
#define JSH     7                     // log2(JCH)

#define TPB_B1  1024
#define NWARP_B (TPB_B1 / 32)         // 32
#define ELEMS_B (KPTS / TPB_B1)       // 2 mask elements per thread
#define FLT_BIG 3.402823466e38f

// partial top-2 (true squared distances, +sq_i applied), layout [b][cj][i]
__device__ float2 g_part[BATCH * JS * KPTS];

__device__ __forceinline__ void knn_step(float4 p, float ax, float ay, float az,
                                         float& m1, float& m2) {
    float d = __fmaf_rn(p.x, ax, p.w);
    d = __fmaf_rn(p.y, ay, d);
    d = __fmaf_rn(p.z, az, d);
    float t = fmaxf(m1, d);
    m1 = fminf(m1, d);
    m2 = fminf(m2, t);
}

__device__ __forceinline__ void top2_merge(float c, float& m1, float& m2) {
    float t = fmaxf(m1, c);
    m1 = fminf(m1, c);
    m2 = fminf(m2, t);
}

// ---------------------------------------------------------------------------
// Kernel A: partial 2-NN over one 128-point j-chunk for 512 i-points
// (2 per thread). grid = (4, 16, 16) = 1024 CTAs, 256 threads, 2KB smem.
// A thread has at most one self-point in a given chunk (i0, i1 are 256 apart,
// chunks are 128 wide); the has-self test is warp-uniform.
// ---------------------------------------------------------------------------
__global__ __launch_bounds__(TPB_A)
void sor_knn_partial_kernel(const float* __restrict__ x) {
    __shared__ float4 sp[JCH];   // (x, y, z, |p|^2) for this j-chunk

    const int b   = blockIdx.z;
    const int ci  = blockIdx.x;
    const int cj  = blockIdx.y;
    const int tid = threadIdx.x;
    const float* __restrict__ xb = x + b * 3 * KPTS;
    const int jlo = cj * JCH;

    if (tid < JCH) {   // stage j-chunk
        int g = jlo + tid;
        float px = xb[g];
        float py = xb[KPTS + g];
        float pz = xb[2 * KPTS + g];
        float sq = __fadd_rn(__fadd_rn(__fmul_rn(px, px), __fmul_rn(py, py)),
                             __fmul_rn(pz, pz));
        sp[tid] = make_float4(px, py, pz, sq);
    }
    __syncthreads();

    const int i0 = ci * ICHUNK + tid;
    const int i1 = i0 + TPB_A;

    float x0 = xb[i0], y0 = xb[KPTS + i0], z0 = xb[2 * KPTS + i0];
    float x1 = xb[i1], y1 = xb[KPTS + i1], z1 = xb[2 * KPTS + i1];
    const float ax0 = -2.0f * x0, ay0 = -2.0f * y0, az0 = -2.0f * z0;
    const float ax1 = -2.0f * x1, ay1 = -2.0f * y1, az1 = -2.0f * z1;
    const float si0 = __fadd_rn(__fadd_rn(__fmul_rn(x0, x0), __fmul_rn(y0, y0)),
                                __fmul_rn(z0, z0));
    const float si1 = __fadd_rn(__fadd_rn(__fmul_rn(x1, x1), __fmul_rn(y1, y1)),
                                __fmul_rn(z1, z1));

    float m1a = FLT_BIG, m2a = FLT_BIG;
    float m1b = FLT_BIG, m2b = FLT_BIG;

    // self-point bookkeeping (warp-uniform: i0>>JSH constant within a warp)
    int selfacc = -1, sl = 0;
    if (cj == (i0 >> JSH))      { selfacc = 0; sl = i0 & (JCH - 1); }
    else if (cj == (i1 >> JSH)) { selfacc = 1; sl = i1 & (JCH - 1); }

    if (selfacc < 0) {
        #pragma unroll 8
        for (int j = 0; j < JCH; ++j) {
            float4 p = sp[j];
            knn_step(p, ax0, ay0, az0, m1a, m2a);
            knn_step(p, ax1, ay1, az1, m1b, m2b);
        }
    } else {
        #pragma unroll 4
        for (int j = 0; j < sl; ++j) {
            float4 p = sp[j];
            knn_step(p, ax0, ay0, az0, m1a, m2a);
            knn_step(p, ax1, ay1, az1, m1b, m2b);
        }
        {   // singleton: apply only to the accumulator this is NOT the self of
            float4 p = sp[sl];
            if (selfacc == 0) knn_step(p, ax1, ay1, az1, m1b, m2b);
            else              knn_step(p, ax0, ay0, az0, m1a, m2a);
        }
        #pragma unroll 4
        for (int j = sl + 1; j < JCH; ++j) {
            float4 p = sp[j];
            knn_step(p, ax0, ay0, az0, m1a, m2a);
            knn_step(p, ax1, ay1, az1, m1b, m2b);
        }
    }

    float2* __restrict__ gp = g_part + (b * JS + cj) * KPTS;
    gp[i0] = make_float2(__fadd_rn(m1a, si0), __fadd_rn(m2a, si0));
    gp[i1] = make_float2(__fadd_rn(m1b, si1), __fadd_rn(m2b, si1));
}

// ---------------------------------------------------------------------------
// Kernel B: merge partials -> value, per-batch stats, stable compaction,
// tiled gather. grid = 16, 1024 threads, one CTA per batch.
// ---------------------------------------------------------------------------
__global__ __launch_bounds__(TPB_B1)
void sor_compact_gather_kernel(const float* __restrict__ x,
                               float* __restrict__ out) {
    __shared__ float sx[KPTS];
    __shared__ float sy[KPTS];
    __shared__ float sz[KPTS];
    __shared__ float sval[KPTS];
    __shared__ int   skept[KPTS];
    __shared__ float red[NWARP_B];
    __shared__ int   wofs[NWARP_B];
    __shared__ float s_mean, s_thr;
    __shared__ int   s_n;

    const int b    = blockIdx.x;
    const int tid  = threadIdx.x;
    const int lane = tid & 31;
    const int warp = tid >> 5;
    const float* __restrict__ xb = x + b * 3 * KPTS;
    float* __restrict__ ob = out + b * 3 * KPTS;
    const float2* __restrict__ gp = g_part + b * JS * KPTS;

    #pragma unroll
    for (int t = tid; t < KPTS; t += TPB_B1) {
        sx[t] = xb[t];
        sy[t] = xb[KPTS + t];
        sz[t] = xb[2 * KPTS + t];
        float m1 = FLT_BIG, m2 = FLT_BIG;
        #pragma unroll
        for (int c = 0; c < JS; ++c) {
            float2 pr = gp[c * KPTS + t];     // coalesced per c
            top2_merge(pr.x, m1, m2);
            top2_merge(pr.y, m1, m2);
        }
        sval[t] = __fadd_rn(m1, m2) * 0.5f;
    }
    __syncthreads();

    // ---- mean ----
    float s = 0.0f;
    #pragma unroll
    for (int t = tid; t < KPTS; t += TPB_B1) s += sval[t];
    #pragma unroll
    for (int o = 16; o; o >>= 1) s += __shfl_xor_sync(0xffffffffu, s, o);
    if (lane == 0) red[warp] = s;
    __syncthreads();
    if (warp == 0) {
        float v = red[lane];
        #pragma unroll
        for (int o = 16; o; o >>= 1) v += __shfl_xor_sync(0xffffffffu, v, o);
        if (lane == 0) s_mean = v * (1.0f / (float)KPTS);
    }
    __syncthreads();
    const float mean = s_mean;

    // ---- std (ddof = 1) ----
    float s2 = 0.0f;
    #pragma unroll
    for (int t = tid; t < KPTS; t += TPB_B1) {
        float d = sval[t] - mean;
        s2 = __fmaf_rn(d, d, s2);
    }
    #pragma unroll
    for (int o = 16; o; o >>= 1) s2 += __shfl_xor_sync(0xffffffffu, s2, o);
    if (lane == 0) red[warp] = s2;
    __syncthreads();
    if (warp == 0) {
        float v = red[lane];
        #pragma unroll
        for (int o = 16; o; o >>= 1) v += __shfl_xor_sync(0xffffffffu, v, o);
        if (lane == 0) {
            float var = v / (float)(KPTS - 1);
            s_thr = __fadd_rn(s_mean, __fmul_rn(1.1f, sqrtf(var)));
        }
    }
    __syncthreads();
    const float thr = s_thr;

    // ---- stable compaction: thread owns ELEMS_B contiguous indices ----
    const int base_t = tid * ELEMS_B;
    unsigned mbits = 0;
    int c = 0;
    #pragma unroll
    for (int u = 0; u < ELEMS_B; ++u) {
        bool m = sval[base_t + u] <= thr;
        mbits |= (unsigned)m << u;
        c += (int)m;
    }
    int v = c;
    #pragma unroll
    for (int o = 1; o < 32; o <<= 1) {
        int t2 = __shfl_up_sync(0xffffffffu, v, o);
        if (lane >= o) v += t2;
    }
    if (lane == 31) wofs[warp] = v;    // warp totals
    __syncthreads();
    if (warp == 0) {
        int wv = wofs[lane];
        int inc = wv;
        #pragma unroll
        for (int o = 1; o < 32; o <<= 1) {
            int t3 = __shfl_up_sync(0xffffffffu, inc, o);
            if (lane >= o) inc += t3;
        }
        wofs[lane] = inc - wv;          // exclusive warp offsets
        if (lane == 31) s_n = inc;      // total kept
    }
    __syncthreads();
    int pos = (v - c) + wofs[warp];
    #pragma unroll
    for (int u = 0; u < ELEMS_B; ++u) {
        if ((mbits >> u) & 1u) skept[pos++] = base_t + u;
    }
    __syncthreads();

    // ---- tiled gather: out[:, j] = pts[kept[j mod n]] ----
    const int n = s_n;   // >= 1 always
    #pragma unroll
    for (int j = tid; j < NPOINT; j += TPB_B1) {
        int p = (j < n) ? j : (j % n);
        int idx = skept[p];
        ob[j]            = sx[idx];
        ob[KPTS + j]     = sy[idx];
        ob[2 * KPTS + j] = sz[idx];
    }
}

extern "C" void kernel_launch(void* const* d_in, const int* in_sizes, int n_in,
                              void* d_out, int out_size) {
    (void)in_sizes; (void)n_in; (void)out_size;
    const float* x = (const float*)d_in[0];
    float* out = (float*)d_out;

    sor_knn_partial_kernel<<<dim3(NI_CH, JS, BATCH), TPB_A>>>(x);
    sor_compact_gather_kernel<<<BATCH, TPB_B1>>>(x, out);
}

// round 5
// speedup vs baseline: 1.0666x; 1.0666x over previous
#include <cuda_runtime.h>

#define BATCH   16
#define KPTS    2048
#define NPOINT  2048

#define TPB_A   128
#define IBLK    2
#define ICHUNK  (TPB_A * IBLK)        // 256 i-points per CTA
#define NI_CH   (KPTS / ICHUNK)       // 8
#define JS      16                    // j-splits
#define JCH     (KPTS / JS)           // 128 j-points per CTA (== TPB_A)

#define TPB_B1  1024
#define NWARP_B (TPB_B1 / 32)         // 32
#define ELEMS_B (KPTS / TPB_B1)       // 2 mask elements per thread
#define FLT_BIG 3.402823466e38f

// partial top-2 (true squared distances, +sq_i applied), layout [b][cj][i]
__device__ float2 g_part[BATCH * JS * KPTS];
// merged per-point kNN mean value
__device__ float  g_value[BATCH * KPTS];

__device__ __forceinline__ void knn_step(float4 p, float ax, float ay, float az,
                                         float& m1, float& m2) {
    float d = __fmaf_rn(p.x, ax, p.w);
    d = __fmaf_rn(p.y, ay, d);
    d = __fmaf_rn(p.z, az, d);
    float t = fmaxf(m1, d);
    m1 = fminf(m1, d);
    m2 = fminf(m2, t);
}

__device__ __forceinline__ void top2_merge(float c, float& m1, float& m2) {
    float t = fmaxf(m1, c);
    m1 = fminf(m1, c);
    m2 = fminf(m2, t);
}

// ---------------------------------------------------------------------------
// Kernel A: partial 2-NN over one 128-point j-chunk for 256 i-points
// (2 per thread). grid = (8, 16, 16) = 2048 CTAs x 128 threads = 262K threads.
// 128-thr CTAs @ 32 regs -> 16 CTAs/SM capacity (2368 slots) >= 2048 CTAs:
// the whole grid is resident in ONE wave, no quantization tail.
// i0 lives in j-chunk 2*ci (local idx tid), i1 in chunk 2*ci+1 (local idx tid).
// ---------------------------------------------------------------------------
__global__ __launch_bounds__(TPB_A)
void sor_knn_partial_kernel(const float* __restrict__ x) {
    __shared__ float4 sp[JCH];   // (x, y, z, |p|^2) for this j-chunk

    const int b   = blockIdx.z;
    const int ci  = blockIdx.x;
    const int cj  = blockIdx.y;
    const int tid = threadIdx.x;
    const float* __restrict__ xb = x + b * 3 * KPTS;

    {   // stage j-chunk (one element per thread: JCH == TPB_A)
        int g = cj * JCH + tid;
        float px = xb[g];
        float py = xb[KPTS + g];
        float pz = xb[2 * KPTS + g];
        float sq = __fadd_rn(__fadd_rn(__fmul_rn(px, px), __fmul_rn(py, py)),
                             __fmul_rn(pz, pz));
        sp[tid] = make_float4(px, py, pz, sq);
    }
    __syncthreads();

    const int i0 = ci * ICHUNK + tid;
    const int i1 = i0 + TPB_A;

    float x0 = xb[i0], y0 = xb[KPTS + i0], z0 = xb[2 * KPTS + i0];
    float x1 = xb[i1], y1 = xb[KPTS + i1], z1 = xb[2 * KPTS + i1];
    const float ax0 = -2.0f * x0, ay0 = -2.0f * y0, az0 = -2.0f * z0;
    const float ax1 = -2.0f * x1, ay1 = -2.0f * y1, az1 = -2.0f * z1;
    const float si0 = __fadd_rn(__fadd_rn(__fmul_rn(x0, x0), __fmul_rn(y0, y0)),
                                __fmul_rn(z0, z0));
    const float si1 = __fadd_rn(__fadd_rn(__fmul_rn(x1, x1), __fmul_rn(y1, y1)),
                                __fmul_rn(z1, z1));

    float m1a = FLT_BIG, m2a = FLT_BIG;
    float m1b = FLT_BIG, m2b = FLT_BIG;

    const int selfacc = (cj == 2 * ci) ? 0 : ((cj == 2 * ci + 1) ? 1 : -1);

    if (selfacc < 0) {
        #pragma unroll 8
        for (int j = 0; j < JCH; ++j) {
            float4 p = sp[j];
            knn_step(p, ax0, ay0, az0, m1a, m2a);
            knn_step(p, ax1, ay1, az1, m1b, m2b);
        }
    } else {
        const int l = tid;
        #pragma unroll 4
        for (int j = 0; j < l; ++j) {
            float4 p = sp[j];
            knn_step(p, ax0, ay0, az0, m1a, m2a);
            knn_step(p, ax1, ay1, az1, m1b, m2b);
        }
        {   // singleton: apply only to the accumulator this is NOT the self of
            float4 p = sp[l];
            if (selfacc == 0) knn_step(p, ax1, ay1, az1, m1b, m2b);
            else              knn_step(p, ax0, ay0, az0, m1a, m2a);
        }
        #pragma unroll 4
        for (int j = l + 1; j < JCH; ++j) {
            float4 p = sp[j];
            knn_step(p, ax0, ay0, az0, m1a, m2a);
            knn_step(p, ax1, ay1, az1, m1b, m2b);
        }
    }

    float2* __restrict__ gp = g_part + (b * JS + cj) * KPTS;
    gp[i0] = make_float2(__fadd_rn(m1a, si0), __fadd_rn(m2a, si0));
    gp[i1] = make_float2(__fadd_rn(m1b, si1), __fadd_rn(m2b, si1));
}

// ---------------------------------------------------------------------------
// Kernel B0: merge JS partial top-2's -> per-point kNN mean value.
// grid = 128 CTAs x 256 threads, one point per thread, JS independent loads.
// ---------------------------------------------------------------------------
__global__ __launch_bounds__(256)
void sor_merge_kernel() {
    const int g = blockIdx.x * 256 + threadIdx.x;   // [0, BATCH*KPTS)
    const int b = g >> 11;
    const int i = g & (KPTS - 1);

    float m1 = FLT_BIG, m2 = FLT_BIG;
    #pragma unroll
    for (int c = 0; c < JS; ++c) {
        float2 pr = g_part[(b * JS + c) * KPTS + i];
        top2_merge(pr.x, m1, m2);
        top2_merge(pr.y, m1, m2);
    }
    g_value[g] = __fadd_rn(m1, m2) * 0.5f;
}

// ---------------------------------------------------------------------------
// Kernel B1: per-batch stats + stable compaction + tiled gather.
// grid = 16, 1024 threads, one CTA per batch.
// ---------------------------------------------------------------------------
__global__ __launch_bounds__(TPB_B1)
void sor_compact_gather_kernel(const float* __restrict__ x,
                               float* __restrict__ out) {
    __shared__ float sx[KPTS];
    __shared__ float sy[KPTS];
    __shared__ float sz[KPTS];
    __shared__ float sval[KPTS];
    __shared__ int   skept[KPTS];
    __shared__ float red[NWARP_B];
    __shared__ int   wofs[NWARP_B];
    __shared__ float s_mean, s_thr;
    __shared__ int   s_n;

    const int b    = blockIdx.x;
    const int tid  = threadIdx.x;
    const int lane = tid & 31;
    const int warp = tid >> 5;
    const float* __restrict__ xb = x + b * 3 * KPTS;
    float* __restrict__ ob = out + b * 3 * KPTS;

    #pragma unroll
    for (int t = tid; t < KPTS; t += TPB_B1) {
        sx[t]   = xb[t];
        sy[t]   = xb[KPTS + t];
        sz[t]   = xb[2 * KPTS + t];
        sval[t] = g_value[b * KPTS + t];
    }
    __syncthreads();

    // ---- mean ----
    float s = 0.0f;
    #pragma unroll
    for (int t = tid; t < KPTS; t += TPB_B1) s += sval[t];
    #pragma unroll
    for (int o = 16; o; o >>= 1) s += __shfl_xor_sync(0xffffffffu, s, o);
    if (lane == 0) red[warp] = s;
    __syncthreads();
    if (warp == 0) {
        float v = red[lane];
        #pragma unroll
        for (int o = 16; o; o >>= 1) v += __shfl_xor_sync(0xffffffffu, v, o);
        if (lane == 0) s_mean = v * (1.0f / (float)KPTS);
    }
    __syncthreads();
    const float mean = s_mean;

    // ---- std (ddof = 1) ----
    float s2 = 0.0f;
    #pragma unroll
    for (int t = tid; t < KPTS; t += TPB_B1) {
        float d = sval[t] - mean;
        s2 = __fmaf_rn(d, d, s2);
    }
    #pragma unroll
    for (int o = 16; o; o >>= 1) s2 += __shfl_xor_sync(0xffffffffu, s2, o);
    if (lane == 0) red[warp] = s2;
    __syncthreads();
    if (warp == 0) {
        float v = red[lane];
        #pragma unroll
        for (int o = 16; o; o >>= 1) v += __shfl_xor_sync(0xffffffffu, v, o);
        if (lane == 0) {
            float var = v / (float)(KPTS - 1);
            s_thr = __fadd_rn(s_mean, __fmul_rn(1.1f, sqrtf(var)));
        }
    }
    __syncthreads();
    const float thr = s_thr;

    // ---- stable compaction: thread owns ELEMS_B contiguous indices ----
    const int base_t = tid * ELEMS_B;
    unsigned mbits = 0;
    int c = 0;
    #pragma unroll
    for (int u = 0; u < ELEMS_B; ++u) {
        bool m = sval[base_t + u] <= thr;
        mbits |= (unsigned)m << u;
        c += (int)m;
    }
    int v = c;
    #pragma unroll
    for (int o = 1; o < 32; o <<= 1) {
        int t2 = __shfl_up_sync(0xffffffffu, v, o);
        if (lane >= o) v += t2;
    }
    if (lane == 31) wofs[warp] = v;    // warp totals
    __syncthreads();
    if (warp == 0) {
        int wv = wofs[lane];
        int inc = wv;
        #pragma unroll
        for (int o = 1; o < 32; o <<= 1) {
            int t3 = __shfl_up_sync(0xffffffffu, inc, o);
            if (lane >= o) inc += t3;
        }
        wofs[lane] = inc - wv;          // exclusive warp offsets
        if (lane == 31) s_n = inc;      // total kept
    }
    __syncthreads();
    int pos = (v - c) + wofs[warp];
    #pragma unroll
    for (int u = 0; u < ELEMS_B; ++u) {
        if ((mbits >> u) & 1u) skept[pos++] = base_t + u;
    }
    __syncthreads();

    // ---- tiled gather: out[:, j] = pts[kept[j mod n]] ----
    const int n = s_n;   // >= 1 always
    #pragma unroll
    for (int j = tid; j < NPOINT; j += TPB_B1) {
        int p = (j < n) ? j : (j % n);
        int idx = skept[p];
        ob[j]            = sx[idx];
        ob[KPTS + j]     = sy[idx];
        ob[2 * KPTS + j] = sz[idx];
    }
}

extern "C" void kernel_launch(void* const* d_in, const int* in_sizes, int n_in,
                              void* d_out, int out_size) {
    (void)in_sizes; (void)n_in; (void)out_size;
    const float* x = (const float*)d_in[0];
    float* out = (float*)d_out;

    sor_knn_partial_kernel<<<dim3(NI_CH, JS, BATCH), TPB_A>>>(x);
    sor_merge_kernel<<<(BATCH * KPTS) / 256, 256>>>();
    sor_compact_gather_kernel<<<BATCH, TPB_B1>>>(x, out);
}

// round 7
// speedup vs baseline: 1.1427x; 1.0713x over previous
#include <cuda_runtime.h>

#define BATCH   16
#define KPTS    2048
#define NPOINT  2048

#define TPB_A   128
#define ICHUNK  (TPB_A * 2)           // 256 i-points per CTA (2 per thread)
#define NI_CH   (KPTS / ICHUNK)       // 8
#define JS      16                    // j-splits
#define JCH     (KPTS / JS)           // 128 j-points per chunk (== TPB_A)

#define TPB_B1  1024
#define NWARP_B (TPB_B1 / 32)         // 32
#define ELEMS_B (KPTS / TPB_B1)       // 2
#define FLT_BIG 3.402823466e38f

typedef unsigned long long u64;

// per-(batch, chunk, i) top-3 candidates (true squared distances, +sq_i),
// FLT_BIG padding where a chunk only contributes 2.
__device__ float4 g_part[BATCH * JS * KPTS];
__device__ float  g_value[BATCH * KPTS];

// ---- packed f32x2 helpers (sm_100a: fma.rn.f32x2 exists; min/max do NOT) ---
__device__ __forceinline__ u64 f2pack(float lo, float hi) {
    u64 r; asm("mov.b64 %0, {%1, %2};" : "=l"(r) : "f"(lo), "f"(hi)); return r;
}
__device__ __forceinline__ u64 fma2(u64 a, u64 b, u64 c) {
    u64 d; asm("fma.rn.f32x2 %0, %1, %2, %3;" : "=l"(d) : "l"(a), "l"(b), "l"(c));
    return d;
}
__device__ __forceinline__ void f2unpack(u64 v, float& lo, float& hi) {
    asm("mov.b64 {%0, %1}, %2;" : "=f"(lo), "=f"(hi) : "l"(v));
}

__device__ __forceinline__ void s_top2(float c, float& m1, float& m2) {
    float t = fmaxf(m1, c); m1 = fminf(m1, c); m2 = fminf(m2, t);
}
__device__ __forceinline__ void s_top3(float c, float& m1, float& m2, float& m3) {
    float t1 = fmaxf(m1, c); m1 = fminf(m1, c);
    float t2 = fmaxf(m2, t1); m2 = fminf(m2, t1); m3 = fminf(m3, t2);
}

// ---- packed chunk scan ------------------------------------------------------
// Two accumulators (i0, i1); distances for 2 j's at a time via fma.rn.f32x2;
// two scalar top-k chains per accumulator (lo-lane j's and hi-lane j's).
// TA/TB = 3 for the accumulator whose self lies in this chunk, else 2.
template<int TA, int TB>
__device__ __forceinline__ void scan_chunk(
    const ulonglong2* __restrict__ px2, const ulonglong2* __restrict__ py2,
    const ulonglong2* __restrict__ pz2, const ulonglong2* __restrict__ pw2,
    u64 ax0, u64 ay0, u64 az0, u64 ax1, u64 ay1, u64 az1,
    float* A, float* B)   // A[0..2*TA), B[0..2*TB): {even chain, odd chain}
{
    #pragma unroll 4
    for (int q = 0; q < JCH / 4; ++q) {
        ulonglong2 X = px2[q], Y = py2[q], Z = pz2[q], W = pw2[q];

        u64 d01 = fma2(Z.x, az0, fma2(Y.x, ay0, fma2(X.x, ax0, W.x)));
        u64 d23 = fma2(Z.y, az0, fma2(Y.y, ay0, fma2(X.y, ax0, W.y)));
        float l0, h0, l1, h1;
        f2unpack(d01, l0, h0); f2unpack(d23, l1, h1);
        if (TA == 3) {
            s_top3(l0, A[0], A[1], A[2]); s_top3(h0, A[3], A[4], A[5]);
            s_top3(l1, A[0], A[1], A[2]); s_top3(h1, A[3], A[4], A[5]);
        } else {
            s_top2(l0, A[0], A[1]); s_top2(h0, A[2], A[3]);
            s_top2(l1, A[0], A[1]); s_top2(h1, A[2], A[3]);
        }

        u64 e01 = fma2(Z.x, az1, fma2(Y.x, ay1, fma2(X.x, ax1, W.x)));
        u64 e23 = fma2(Z.y, az1, fma2(Y.y, ay1, fma2(X.y, ax1, W.y)));
        f2unpack(e01, l0, h0); f2unpack(e23, l1, h1);
        if (TB == 3) {
            s_top3(l0, B[0], B[1], B[2]); s_top3(h0, B[3], B[4], B[5]);
            s_top3(l1, B[0], B[1], B[2]); s_top3(h1, B[3], B[4], B[5]);
        } else {
            s_top2(l0, B[0], B[1]); s_top2(h0, B[2], B[3]);
            s_top2(l1, B[0], B[1]); s_top2(h1, B[2], B[3]);
        }
    }
}

// merge the two chains (exact min/max union), add si to survivors
__device__ __forceinline__ float4 fin2(const float* C, float si) {
    float M1 = C[0], M2 = C[1];
    s_top2(C[2], M1, M2);
    s_top2(C[3], M1, M2);
    return make_float4(__fadd_rn(M1, si), __fadd_rn(M2, si), FLT_BIG, FLT_BIG);
}
__device__ __forceinline__ float4 fin3(const float* C, float si) {
    float M1 = C[0], M2 = C[1], M3 = C[2];
    s_top3(C[3], M1, M2, M3);
    s_top3(C[4], M1, M2, M3);
    s_top3(C[5], M1, M2, M3);
    return make_float4(__fadd_rn(M1, si), __fadd_rn(M2, si), __fadd_rn(M3, si),
                       FLT_BIG);
}

// ---------------------------------------------------------------------------
// Kernel A: packed partial kNN. grid = (8, 16, 16) = 2048 CTAs x 128 threads.
// Self is INCLUDED (top-3 on the one accumulator whose self is in this chunk);
// the global merge drops the minimum == reference top_k(k+1)/drop-smallest.
// ---------------------------------------------------------------------------
__global__ __launch_bounds__(TPB_A)
void sor_knn_partial_kernel(const float* __restrict__ x) {
    __shared__ __align__(16) float spx[JCH];
    __shared__ __align__(16) float spy[JCH];
    __shared__ __align__(16) float spz[JCH];
    __shared__ __align__(16) float spw[JCH];

    const int b   = blockIdx.z;
    const int ci  = blockIdx.x;
    const int cj  = blockIdx.y;
    const int tid = threadIdx.x;
    const float* __restrict__ xb = x + b * 3 * KPTS;

    {   // stage j-chunk in SoA form (JCH == TPB_A)
        int g = cj * JCH + tid;
        float px = xb[g];
        float py = xb[KPTS + g];
        float pz = xb[2 * KPTS + g];
        float sq = __fadd_rn(__fadd_rn(__fmul_rn(px, px), __fmul_rn(py, py)),
                             __fmul_rn(pz, pz));
        spx[tid] = px; spy[tid] = py; spz[tid] = pz; spw[tid] = sq;
    }
    __syncthreads();

    const int i0 = ci * ICHUNK + tid;
    const int i1 = i0 + TPB_A;

    float x0 = xb[i0], y0 = xb[KPTS + i0], z0 = xb[2 * KPTS + i0];
    float x1 = xb[i1], y1 = xb[KPTS + i1], z1 = xb[2 * KPTS + i1];
    const u64 ax0 = f2pack(-2.0f * x0, -2.0f * x0);
    const u64 ay0 = f2pack(-2.0f * y0, -2.0f * y0);
    const u64 az0 = f2pack(-2.0f * z0, -2.0f * z0);
    const u64 ax1 = f2pack(-2.0f * x1, -2.0f * x1);
    const u64 ay1 = f2pack(-2.0f * y1, -2.0f * y1);
    const u64 az1 = f2pack(-2.0f * z1, -2.0f * z1);
    const float si0 = __fadd_rn(__fadd_rn(__fmul_rn(x0, x0), __fmul_rn(y0, y0)),
                                __fmul_rn(z0, z0));
    const float si1 = __fadd_rn(__fadd_rn(__fmul_rn(x1, x1), __fmul_rn(y1, y1)),
                                __fmul_rn(z1, z1));

    const ulonglong2* px2 = reinterpret_cast<const ulonglong2*>(spx);
    const ulonglong2* py2 = reinterpret_cast<const ulonglong2*>(spy);
    const ulonglong2* pz2 = reinterpret_cast<const ulonglong2*>(spz);
    const ulonglong2* pw2 = reinterpret_cast<const ulonglong2*>(spw);

    // i0 lives in chunk 2*ci, i1 in chunk 2*ci+1
    const int selfacc = (cj == 2 * ci) ? 0 : ((cj == 2 * ci + 1) ? 1 : -1);

    float A[6] = {FLT_BIG, FLT_BIG, FLT_BIG, FLT_BIG, FLT_BIG, FLT_BIG};
    float B[6] = {FLT_BIG, FLT_BIG, FLT_BIG, FLT_BIG, FLT_BIG, FLT_BIG};

    float4 r0, r1;
    if (selfacc == 0) {
        scan_chunk<3, 2>(px2, py2, pz2, pw2, ax0, ay0, az0, ax1, ay1, az1, A, B);
        r0 = fin3(A, si0);
        r1 = fin2(B, si1);
    } else if (selfacc == 1) {
        scan_chunk<2, 3>(px2, py2, pz2, pw2, ax0, ay0, az0, ax1, ay1, az1, A, B);
        r0 = fin2(A, si0);
        r1 = fin3(B, si1);
    } else {
        scan_chunk<2, 2>(px2, py2, pz2, pw2, ax0, ay0, az0, ax1, ay1, az1, A, B);
        r0 = fin2(A, si0);
        r1 = fin2(B, si1);
    }

    float4* __restrict__ gp = g_part + (b * JS + cj) * KPTS;
    gp[i0] = r0;
    gp[i1] = r1;
}

// ---------------------------------------------------------------------------
// Kernel B0: global top-3 across chunks, drop min (self), value = (m2+m3)/2.
// grid = 128 CTAs x 256 threads.
// ---------------------------------------------------------------------------
__global__ __launch_bounds__(256)
void sor_merge_kernel() {
    const int g = blockIdx.x * 256 + threadIdx.x;   // [0, BATCH*KPTS)
    const int b = g >> 11;
    const int i = g & (KPTS - 1);

    float m1 = FLT_BIG, m2 = FLT_BIG, m3 = FLT_BIG;
    #pragma unroll
    for (int c = 0; c < JS; ++c) {
        float4 pr = g_part[(b * JS + c) * KPTS + i];
        s_top3(pr.x, m1, m2, m3);
        s_top3(pr.y, m1, m2, m3);
        s_top3(pr.z, m1, m2, m3);
    }
    // m1 == self (~0), dropped; mean of the two true nearest
    g_value[g] = __fadd_rn(m2, m3) * 0.5f;
}

// ---------------------------------------------------------------------------
// Kernel B1: per-batch stats + stable compaction + tiled gather.
// grid = 16, 1024 threads.
// ---------------------------------------------------------------------------
__global__ __launch_bounds__(TPB_B1)
void sor_compact_gather_kernel(const float* __restrict__ x,
                               float* __restrict__ out) {
    __shared__ float sx[KPTS];
    __shared__ float sy[KPTS];
    __shared__ float sz[KPTS];
    __shared__ float sval[KPTS];
    __shared__ int   skept[KPTS];
    __shared__ float red[NWARP_B];
    __shared__ int   wofs[NWARP_B];
    __shared__ float s_mean, s_thr;
    __shared__ int   s_n;

    const int b    = blockIdx.x;
    const int tid  = threadIdx.x;
    const int lane = tid & 31;
    const int warp = tid >> 5;
    const float* __restrict__ xb = x + b * 3 * KPTS;
    float* __restrict__ ob = out + b * 3 * KPTS;

    #pragma unroll
    for (int t = tid; t < KPTS; t += TPB_B1) {
        sx[t]   = xb[t];
        sy[t]   = xb[KPTS + t];
        sz[t]   = xb[2 * KPTS + t];
        sval[t] = g_value[b * KPTS + t];
    }
    __syncthreads();

    // ---- mean ----
    float s = 0.0f;
    #pragma unroll
    for (int t = tid; t < KPTS; t += TPB_B1) s += sval[t];
    #pragma unroll
    for (int o = 16; o; o >>= 1) s += __shfl_xor_sync(0xffffffffu, s, o);
    if (lane == 0) red[warp] = s;
    __syncthreads();
    if (warp == 0) {
        float v = red[lane];
        #pragma unroll
        for (int o = 16; o; o >>= 1) v += __shfl_xor_sync(0xffffffffu, v, o);
        if (lane == 0) s_mean = v * (1.0f / (float)KPTS);
    }
    __syncthreads();
    const float mean = s_mean;

    // ---- std (ddof = 1) ----
    float s2 = 0.0f;
    #pragma unroll
    for (int t = tid; t < KPTS; t += TPB_B1) {
        float d = sval[t] - mean;
        s2 = __fmaf_rn(d, d, s2);
    }
    #pragma unroll
    for (int o = 16; o; o >>= 1) s2 += __shfl_xor_sync(0xffffffffu, s2, o);
    if (lane == 0) red[warp] = s2;
    __syncthreads();
    if (warp == 0) {
        float v = red[lane];
        #pragma unroll
        for (int o = 16; o; o >>= 1) v += __shfl_xor_sync(0xffffffffu, v, o);
        if (lane == 0) {
            float var = v / (float)(KPTS - 1);
            s_thr = __fadd_rn(s_mean, __fmul_rn(1.1f, sqrtf(var)));
        }
    }
    __syncthreads();
    const float thr = s_thr;

    // ---- stable compaction ----
    const int base_t = tid * ELEMS_B;
    unsigned mbits = 0;
    int c = 0;
    #pragma unroll
    for (int u = 0; u < ELEMS_B; ++u) {
        bool m = sval[base_t + u] <= thr;
        mbits |= (unsigned)m << u;
        c += (int)m;
    }
    int v = c;
    #pragma unroll
    for (int o = 1; o < 32; o <<= 1) {
        int t2 = __shfl_up_sync(0xffffffffu, v, o);
        if (lane >= o) v += t2;
    }
    if (lane == 31) wofs[warp] = v;
    __syncthreads();
    if (warp == 0) {
        int wv = wofs[lane];
        int inc = wv;
        #pragma unroll
        for (int o = 1; o < 32; o <<= 1) {
            int t3 = __shfl_up_sync(0xffffffffu, inc, o);
            if (lane >= o) inc += t3;
        }
        wofs[lane] = inc - wv;
        if (lane == 31) s_n = inc;
    }
    __syncthreads();
    int pos = (v - c) + wofs[warp];
    #pragma unroll
    for (int u = 0; u < ELEMS_B; ++u) {
        if ((mbits >> u) & 1u) skept[pos++] = base_t + u;
    }
    __syncthreads();

    // ---- tiled gather ----
    const int n = s_n;
    #pragma unroll
    for (int j = tid; j < NPOINT; j += TPB_B1) {
        int p = (j < n) ? j : (j % n);
        int idx = skept[p];
        ob[j]            = sx[idx];
        ob[KPTS + j]     = sy[idx];
        ob[2 * KPTS + j] = sz[idx];
    }
}

extern "C" void kernel_launch(void* const* d_in, const int* in_sizes, int n_in,
                              void* d_out, int out_size) {
    (void)in_sizes; (void)n_in; (void)out_size;
    const float* x = (const float*)d_in[0];
    float* out = (float*)d_out;

    sor_knn_partial_kernel<<<dim3(NI_CH, JS, BATCH), TPB_A>>>(x);
    sor_merge_kernel<<<(BATCH * KPTS) / 256, 256>>>();
    sor_compact_gather_kernel<<<BATCH, TPB_B1>>>(x, out);
}